// round 2
// baseline (speedup 1.0000x reference)
#include <cuda_runtime.h>
#include <cstdint>

// Problem constants
#define NVv 1024
#define NHh 512
#define TTt 128
#define BBb 256
#define TB  32768              // T*B columns
#define VELEMS (1024u*32768u)  // v_model element count

// ---------------- static device scratch (no cudaMalloc allowed) ----------
__device__ float g_Wv[(size_t)NHh * TB];    // W @ v_data           (64 MB)
__device__ float g_ubase[(size_t)NHh * TB]; // b_init / U@r_{t-1}   (64 MB)
__device__ float g_h[(size_t)NHh * TB];     // h_model bits as f32  (64 MB)
__device__ float g_part[4][NHh * BBb];      // split-K partials     ( 2 MB)

// ---------------- threefry2x32 (20 rounds), JAX-compatible ----------------
__host__ __device__ __forceinline__ uint32_t rotl32(uint32_t x, int r) {
    return (x << r) | (x >> (32 - r));
}

__host__ __device__ inline void threefry2x32(uint32_t k0, uint32_t k1,
                                             uint32_t x0, uint32_t x1,
                                             uint32_t& o0, uint32_t& o1) {
    uint32_t k2 = k0 ^ k1 ^ 0x1BD11BDAu;
    x0 += k0; x1 += k1;
    // group 1: rotations {13,15,26,6}
    x0 += x1; x1 = rotl32(x1, 13); x1 ^= x0;
    x0 += x1; x1 = rotl32(x1, 15); x1 ^= x0;
    x0 += x1; x1 = rotl32(x1, 26); x1 ^= x0;
    x0 += x1; x1 = rotl32(x1,  6); x1 ^= x0;
    x0 += k1; x1 += k2 + 1u;
    // group 2: rotations {17,29,16,24}
    x0 += x1; x1 = rotl32(x1, 17); x1 ^= x0;
    x0 += x1; x1 = rotl32(x1, 29); x1 ^= x0;
    x0 += x1; x1 = rotl32(x1, 16); x1 ^= x0;
    x0 += x1; x1 = rotl32(x1, 24); x1 ^= x0;
    x0 += k2; x1 += k0 + 2u;
    // group 3
    x0 += x1; x1 = rotl32(x1, 13); x1 ^= x0;
    x0 += x1; x1 = rotl32(x1, 15); x1 ^= x0;
    x0 += x1; x1 = rotl32(x1, 26); x1 ^= x0;
    x0 += x1; x1 = rotl32(x1,  6); x1 ^= x0;
    x0 += k0; x1 += k1 + 3u;
    // group 4
    x0 += x1; x1 = rotl32(x1, 17); x1 ^= x0;
    x0 += x1; x1 = rotl32(x1, 29); x1 ^= x0;
    x0 += x1; x1 = rotl32(x1, 16); x1 ^= x0;
    x0 += x1; x1 = rotl32(x1, 24); x1 ^= x0;
    x0 += k1; x1 += k2 + 4u;
    // group 5
    x0 += x1; x1 = rotl32(x1, 13); x1 ^= x0;
    x0 += x1; x1 = rotl32(x1, 15); x1 ^= x0;
    x0 += x1; x1 = rotl32(x1, 26); x1 ^= x0;
    x0 += x1; x1 = rotl32(x1,  6); x1 ^= x0;
    x0 += k2; x1 += k0 + 5u;
    o0 = x0; o1 = x1;
}

// JAX partitionable random_bits(32): counter = flat index (hi word 0),
// bits = o0 ^ o1. uniform = bitcast((bits>>9)|0x3f800000) - 1.
__device__ __forceinline__ float uniform01(uint32_t ka, uint32_t kb, uint32_t idx) {
    uint32_t o0, o1;
    threefry2x32(ka, kb, 0u, idx, o0, o1);
    uint32_t bits = o0 ^ o1;
    return __uint_as_float((bits >> 9) | 0x3f800000u) - 1.0f;
}

// ---------------- accurate exp/sigmoid (fast-math-proof, ~1 ulp) ---------
__device__ __forceinline__ float exp_acc(float x) {
    x = fminf(fmaxf(x, -87.0f), 87.0f);
    float t = fmaf(x, 1.4426950408889634f, 12582912.0f);
    float n = t - 12582912.0f;                     // round-to-nearest int
    float r = fmaf(n, -0.693145751953125f, x);     // ln2_hi
    r = fmaf(n, -1.42860676533018704e-06f, r);     // ln2_lo
    float p = 1.98412698412698413e-04f;            // 1/5040
    p = fmaf(p, r, 1.38888888888888889e-03f);      // 1/720
    p = fmaf(p, r, 8.33333333333333333e-03f);      // 1/120
    p = fmaf(p, r, 4.16666666666666667e-02f);      // 1/24
    p = fmaf(p, r, 1.66666666666666667e-01f);      // 1/6
    p = fmaf(p, r, 0.5f);
    p = fmaf(p, r, 1.0f);
    p = fmaf(p, r, 1.0f);
    int i = (int)n;
    float sc = __int_as_float((uint32_t)(i + 127) << 23);
    return p * sc;
}

__device__ __forceinline__ float sigmoid_ref(float x) {
    float e = exp_acc(-x);
    return __fdiv_rn(1.0f, __fadd_rn(1.0f, e));
}

// ---------------- big GEMM: C(M x 32768) = op(A)(M x K) * B(K x 32768) ---
// TRANSA=false: A row-major MxK (lda = row stride). TRANSA=true: A(m,k)=A[k*lda+m].
// EPI 0: store raw C. EPI 1: bern(sigmoid(c + bias[m])). EPI 2: bern(sigmoid(
//        (c + ubase[idx]) [+ bias[m] if t>0] )).
template <bool TRANSA, int EPI>
__global__ void __launch_bounds__(256, 2)
gemm_big(const float* __restrict__ A, const float* __restrict__ B,
         int K, int lda, float* __restrict__ Cout,
         const float* __restrict__ bias, const float* __restrict__ ubase,
         uint32_t ka, uint32_t kb)
{
    __shared__ float As[16][128];   // [k][m]
    __shared__ float Bs[16][128];   // [k][n]
    const int tid = threadIdx.x;
    const int n0 = blockIdx.x * 128;
    const int m0 = blockIdx.y * 128;
    const int ty = tid >> 4, tx = tid & 15;
    float acc[8][8];
#pragma unroll
    for (int i = 0; i < 8; i++)
#pragma unroll
        for (int j = 0; j < 8; j++) acc[i][j] = 0.0f;

    for (int k0 = 0; k0 < K; k0 += 16) {
        __syncthreads();
#pragma unroll
        for (int s = 0; s < 2; s++) {
            int f = tid + s * 256;
            if (TRANSA) {
                int kk = f >> 5;
                int mm = (f & 31) << 2;
                *(float4*)&As[kk][mm] =
                    *(const float4*)(A + (size_t)(k0 + kk) * lda + m0 + mm);
            } else {
                int ar = f >> 2;
                int ac = (f & 3) << 2;
                float4 v = *(const float4*)(A + (size_t)(m0 + ar) * lda + k0 + ac);
                As[ac + 0][ar] = v.x; As[ac + 1][ar] = v.y;
                As[ac + 2][ar] = v.z; As[ac + 3][ar] = v.w;
            }
            int kk = f >> 5;
            int nn = (f & 31) << 2;
            *(float4*)&Bs[kk][nn] =
                *(const float4*)(B + (size_t)(k0 + kk) * TB + n0 + nn);
        }
        __syncthreads();
#pragma unroll
        for (int kk = 0; kk < 16; kk++) {
            float a[8], bv[8];
            *(float4*)&a[0]  = *(const float4*)&As[kk][ty * 8];
            *(float4*)&a[4]  = *(const float4*)&As[kk][ty * 8 + 4];
            *(float4*)&bv[0] = *(const float4*)&Bs[kk][tx * 8];
            *(float4*)&bv[4] = *(const float4*)&Bs[kk][tx * 8 + 4];
#pragma unroll
            for (int i = 0; i < 8; i++)
#pragma unroll
                for (int j = 0; j < 8; j++)
                    acc[i][j] = fmaf(a[i], bv[j], acc[i][j]);
        }
    }

#pragma unroll
    for (int i = 0; i < 8; i++) {
        int m = m0 + ty * 8 + i;
#pragma unroll
        for (int j = 0; j < 8; j++) {
            int n = n0 + tx * 8 + j;
            size_t o = (size_t)m * TB + n;
            if (EPI == 0) {
                Cout[o] = acc[i][j];
            } else {
                float logit;
                if (EPI == 1) {
                    logit = acc[i][j] + bias[m];
                } else {
                    logit = acc[i][j] + ubase[o];
                    if (n >= 256) logit += bias[m];   // b_h only for t >= 1
                }
                float p = sigmoid_ref(logit);
                float u = uniform01(ka, kb, (uint32_t)o);
                Cout[o] = (u < p) ? 1.0f : 0.0f;
            }
        }
    }
}

// ---------------- recurrence: split-K step GEMM (U @ r_{t-1}) ------------
// M=512, N=256, K=512 split into 4 chunks of 128. Tile 64x64, 4x4/thread.
__global__ void __launch_bounds__(256)
step_gemm(const float* __restrict__ U, const float* __restrict__ rdata, int t)
{
    __shared__ float As[16][64];
    __shared__ float Bs[16][64];
    const int tid = threadIdx.x;
    const int n0 = blockIdx.x * 64;
    const int m0 = blockIdx.y * 64;
    const int kbase = blockIdx.z * 128;
    const int ty = tid >> 4, tx = tid & 15;
    const size_t coloff = (size_t)(t - 1) * 256 + n0;
    float acc[4][4];
#pragma unroll
    for (int i = 0; i < 4; i++)
#pragma unroll
        for (int j = 0; j < 4; j++) acc[i][j] = 0.0f;

    for (int k0 = 0; k0 < 128; k0 += 16) {
        __syncthreads();
        {   // A: 64 rows x 16 cols, transposed store
            int ar = tid >> 2;
            int ac = (tid & 3) << 2;
            float4 v = *(const float4*)(U + (size_t)(m0 + ar) * 512 + kbase + k0 + ac);
            As[ac + 0][ar] = v.x; As[ac + 1][ar] = v.y;
            As[ac + 2][ar] = v.z; As[ac + 3][ar] = v.w;
        }
        {   // B: 16 rows x 64 cols
            int kk = tid >> 4;
            int nn = (tid & 15) << 2;
            *(float4*)&Bs[kk][nn] =
                *(const float4*)(rdata + (size_t)(kbase + k0 + kk) * TB + coloff + nn);
        }
        __syncthreads();
#pragma unroll
        for (int kk = 0; kk < 16; kk++) {
            float a[4], b[4];
            *(float4*)a = *(const float4*)&As[kk][ty * 4];
            *(float4*)b = *(const float4*)&Bs[kk][tx * 4];
#pragma unroll
            for (int i = 0; i < 4; i++)
#pragma unroll
                for (int j = 0; j < 4; j++)
                    acc[i][j] = fmaf(a[i], b[j], acc[i][j]);
        }
    }
    float* dst = g_part[blockIdx.z];
#pragma unroll
    for (int i = 0; i < 4; i++)
#pragma unroll
        for (int j = 0; j < 4; j++)
            dst[(m0 + ty * 4 + i) * 256 + (n0 + tx * 4 + j)] = acc[i][j];
}

// reduce partials, finish step t: ubase = U@r_{t-1}; r_t = sig((Wv+ubase)+b_h)
__global__ void step_epi(const float* __restrict__ b_h,
                         float* __restrict__ rdata, int t)
{
    int i = blockIdx.x * 256 + threadIdx.x;   // 0..131071
    int h = i >> 8, b = i & 255;
    float s = ((g_part[0][i] + g_part[1][i]) + g_part[2][i]) + g_part[3][i];
    size_t o = (size_t)h * TB + (size_t)t * 256 + b;
    float logit = (g_Wv[o] + s) + b_h[h];
    g_ubase[o] = s;
    rdata[o] = sigmoid_ref(logit);
}

// t = 0: ubase = b_init; r0 = sigmoid(Wv0 + b_init)
__global__ void r0_kernel(const float* __restrict__ b_init,
                          float* __restrict__ rdata)
{
    int i = blockIdx.x * 256 + threadIdx.x;   // 0..131071
    int h = i >> 8, b = i & 255;
    float ub = b_init[h];
    size_t o = (size_t)h * TB + b;
    g_ubase[o] = ub;
    rdata[o] = sigmoid_ref(g_Wv[o] + ub);
}

// h1 = bernoulli(sk, r_data)   (parallel_r(v_data, r_data) == r_data exactly)
__global__ void h1_kernel(const float* __restrict__ rdata,
                          uint32_t ka, uint32_t kb)
{
    uint32_t i = blockIdx.x * 256 + threadIdx.x;
    float u = uniform01(ka, kb, i);
    g_h[i] = (u < rdata[i]) ? 1.0f : 0.0f;
}

// ---------------- host driver --------------------------------------------
extern "C" void kernel_launch(void* const* d_in, const int* in_sizes, int n_in,
                              void* d_out, int out_size)
{
    const float* v_data = (const float*)d_in[0];
    const float* W      = (const float*)d_in[1];
    const float* U      = (const float*)d_in[2];
    const float* b_h    = (const float*)d_in[3];
    const float* b_init = (const float*)d_in[4];
    const float* b_v    = (const float*)d_in[5];
    // CDk == 2 (concrete python int in the reference), hardcoded.

    float* vout = (float*)d_out;                 // v_model (1024,128,256)
    float* rout = vout + (size_t)VELEMS;         // r_data  (512,128,256)

    // Derive JAX keys (foldlike split): key(42) = (0,42)
    uint32_t K1a, K1b, ska, skb, K2a, K2b, k1a, k1b, k2a, k2b, kfa, kfb, d0, d1;
    threefry2x32(0u, 42u, 0u, 0u, K1a, K1b);     // key  after 1st split
    threefry2x32(0u, 42u, 0u, 1u, ska, skb);     // sk
    threefry2x32(K1a, K1b, 0u, 0u, K2a, K2b);    // key  after 2nd split
    threefry2x32(K1a, K1b, 0u, 1u, k1a, k1b);    // k1
    threefry2x32(K1a, K1b, 0u, 2u, k2a, k2b);    // k2
    threefry2x32(K2a, K2b, 0u, 0u, d0, d1);      // (unused new key)
    threefry2x32(K2a, K2b, 0u, 1u, kfa, kfb);    // kf
    (void)d0; (void)d1; (void)in_sizes; (void)n_in; (void)out_size;

    void *pWv, *pH, *pUb;
    cudaGetSymbolAddress(&pWv, g_Wv);
    cudaGetSymbolAddress(&pH, g_h);
    cudaGetSymbolAddress(&pUb, g_ubase);
    float* Wv = (float*)pWv;
    float* H  = (float*)pH;
    const float* Ub = (const float*)pUb;

    // 1. Wv = W @ v_data   (512 x 32768, K=1024)
    gemm_big<false, 0><<<dim3(256, 4), 256>>>(W, v_data, 1024, 1024, Wv,
                                              nullptr, nullptr, 0u, 0u);
    // 2. r_0
    r0_kernel<<<512, 256>>>(b_init, rout);
    // 3. sequential recurrence over t = 1..127
    for (int t = 1; t < TTt; t++) {
        step_gemm<<<dim3(4, 8, 4), 256>>>(U, rout, t);
        step_epi<<<512, 256>>>(b_h, rout, t);
    }
    // 4. h1 = bernoulli(sk, r_data)
    h1_kernel<<<65536, 256>>>(rout, ska, skb);
    // 5. v1 = bernoulli(k1, sigmoid(W^T h1 + b_v))  -> vout (scratch)
    gemm_big<true, 1><<<dim3(256, 8), 256>>>(W, H, 512, 1024, vout,
                                             b_v, nullptr, k1a, k1b);
    // 6. h2 = bernoulli(k2, sigmoid(W v1 + ubase (+ b_h for t>0)))
    gemm_big<false, 2><<<dim3(256, 4), 256>>>(W, vout, 1024, 1024, H,
                                              b_h, Ub, k2a, k2b);
    // 7. v_model = bernoulli(kf, sigmoid(W^T h2 + b_v)) -> vout (final)
    gemm_big<true, 1><<<dim3(256, 8), 256>>>(W, H, 512, 1024, vout,
                                             b_v, nullptr, kfa, kfb);
}